// round 2
// baseline (speedup 1.0000x reference)
#include <cuda_runtime.h>

// Problem constants (fixed by the dataset)
#define N_MAX 100000
#define E_MAX 1200000
#define G_MAX 500

// Scratch (device globals; no allocation allowed in kernel_launch)
__device__ __align__(16) float g_deg[N_MAX];
__device__ __align__(16) float g_dis[N_MAX];
__device__ __align__(16) float g_w[E_MAX];
__device__ __align__(16) int   g_src[E_MAX];
__device__ __align__(16) int   g_dst[E_MAX];
__device__ __align__(16) int   g_batch[N_MAX];
__device__ __align__(16) float g_bufA[(size_t)N_MAX * 64];
__device__ __align__(16) float g_bufB[(size_t)N_MAX * 64];
__device__ __align__(16) float g_counts[G_MAX];
__device__ int g_ei_is64;
__device__ int g_batch_is64;

// ---------------------------------------------------------------------------
// Dtype probe: int64 data with values < 2^31 has all odd 32-bit words == 0.
// Samples only the first half of the elements so word index 2k+1 stays in
// bounds under BOTH interpretations.
// ---------------------------------------------------------------------------
__global__ void detect_i64(const int* __restrict__ words, long long n_half, int* flag) {
    __shared__ int ok;
    if (threadIdx.x == 0) ok = 1;
    __syncthreads();
    long long k = (n_half * threadIdx.x) / blockDim.x;
    if (words[2 * k + 1] != 0) ok = 0;   // benign race: only writes 0
    __syncthreads();
    if (threadIdx.x == 0) *flag = ok;
}

// ---------------------------------------------------------------------------
// Prep kernels
// ---------------------------------------------------------------------------
__global__ void prep_edges(const void* __restrict__ ei_raw, int E) {
    int e = blockIdx.x * 256 + threadIdx.x;
    if (e >= E) return;
    if (g_ei_is64) {
        const long long* p = (const long long*)ei_raw;
        g_src[e] = (int)p[e];
        g_dst[e] = (int)p[(size_t)E + e];
    } else {
        const int* p = (const int*)ei_raw;
        g_src[e] = p[e];
        g_dst[e] = p[(size_t)E + e];
    }
}

__global__ void prep_batch(const void* __restrict__ b_raw, int N) {
    int n = blockIdx.x * 256 + threadIdx.x;
    if (n >= N) return;
    if (g_batch_is64) g_batch[n] = (int)((const long long*)b_raw)[n];
    else              g_batch[n] = ((const int*)b_raw)[n];
}

__global__ void init_deg(int N) {
    int n = blockIdx.x * 256 + threadIdx.x;
    if (n < N) g_deg[n] = 1.0f;  // self-loop
}

__global__ void accum_deg(int E) {
    int e = blockIdx.x * 256 + threadIdx.x;
    if (e < E) atomicAdd(&g_deg[g_dst[e]], 1.0f);
}

__global__ void compute_dis(int N) {
    int n = blockIdx.x * 256 + threadIdx.x;
    if (n < N) g_dis[n] = rsqrtf(g_deg[n]);
}

__global__ void compute_w(int E) {
    int e = blockIdx.x * 256 + threadIdx.x;
    if (e < E) g_w[e] = g_dis[g_src[e]] * g_dis[g_dst[e]];
}

// ---------------------------------------------------------------------------
// Dense GEMM: H[N,F] = X[N,K] @ W[K,F]   (W row-major [K,F], cached in smem)
// One thread per row; F accumulators in registers; W reads are smem broadcast.
// ---------------------------------------------------------------------------
template<int K, int F>
__global__ void __launch_bounds__(128) gemm_kernel(const float* __restrict__ X,
                                                   const float* __restrict__ W,
                                                   float* __restrict__ H, int N) {
    __shared__ float Ws[K * F];
    for (int i = threadIdx.x; i < K * F; i += 128) Ws[i] = W[i];
    __syncthreads();

    int row = blockIdx.x * 128 + threadIdx.x;
    if (row >= N) return;

    float acc[F];
#pragma unroll
    for (int f = 0; f < F; f++) acc[f] = 0.0f;

    const float4* x4 = reinterpret_cast<const float4*>(X + (size_t)row * K);
#pragma unroll 2
    for (int k4 = 0; k4 < K / 4; k4++) {
        float4 xv = __ldg(&x4[k4]);
        const float* w0 = &Ws[(k4 * 4 + 0) * F];
        const float* w1 = &Ws[(k4 * 4 + 1) * F];
        const float* w2 = &Ws[(k4 * 4 + 2) * F];
        const float* w3 = &Ws[(k4 * 4 + 3) * F];
#pragma unroll
        for (int f = 0; f < F; f++) {
            acc[f] = fmaf(xv.x, w0[f], acc[f]);
            acc[f] = fmaf(xv.y, w1[f], acc[f]);
            acc[f] = fmaf(xv.z, w2[f], acc[f]);
            acc[f] = fmaf(xv.w, w3[f], acc[f]);
        }
    }

    float4* h4 = reinterpret_cast<float4*>(H + (size_t)row * F);
#pragma unroll
    for (int f4 = 0; f4 < F / 4; f4++)
        h4[f4] = make_float4(acc[4 * f4], acc[4 * f4 + 1], acc[4 * f4 + 2], acc[4 * f4 + 3]);
}

// ---------------------------------------------------------------------------
// Zero buffers
// ---------------------------------------------------------------------------
__global__ void zero4_kernel(float* __restrict__ p, int n4) {
    int i = blockIdx.x * 256 + threadIdx.x;
    if (i < n4) reinterpret_cast<float4*>(p)[i] = make_float4(0.f, 0.f, 0.f, 0.f);
}

__global__ void zero1_kernel(float* __restrict__ p, int n) {
    int i = blockIdx.x * 256 + threadIdx.x;
    if (i < n) p[i] = 0.0f;
}

// ---------------------------------------------------------------------------
// Edge scatter: agg[dst] += h[src] * w[e]
// C = F/4 float4-chunks per row; C consecutive threads handle one edge
// -> coalesced gather + coalesced vectorized red.global.add.v4.f32.
// ---------------------------------------------------------------------------
template<int C>
__global__ void __launch_bounds__(256) scatter_kernel(const float* __restrict__ H,
                                                      float* __restrict__ AGG, int E) {
    unsigned idx = blockIdx.x * 256u + threadIdx.x;
    unsigned e = idx / C;
    unsigned c = idx % C;
    if (e >= (unsigned)E) return;

    int s = g_src[e];
    int d = g_dst[e];
    float wv = g_w[e];

    float4 v = *reinterpret_cast<const float4*>(H + (size_t)s * (4 * C) + c * 4);
    float* p = AGG + (size_t)d * (4 * C) + c * 4;
    asm volatile("red.global.add.v4.f32 [%0], {%1,%2,%3,%4};"
                 :: "l"(p), "f"(v.x * wv), "f"(v.y * wv), "f"(v.z * wv), "f"(v.w * wv)
                 : "memory");
}

// ---------------------------------------------------------------------------
// Finalize: AGG = [relu](AGG + H*dis^2 + bias)
// ---------------------------------------------------------------------------
template<int C, bool RELU>
__global__ void __launch_bounds__(256) finalize_kernel(float* __restrict__ AGG,
                                                       const float* __restrict__ H,
                                                       const float* __restrict__ bias,
                                                       int N) {
    unsigned idx = blockIdx.x * 256u + threadIdx.x;
    unsigned n = idx / C;
    unsigned c = idx % C;
    if (n >= (unsigned)N) return;

    float w = g_dis[n];
    w *= w;
    float4 a = *reinterpret_cast<const float4*>(AGG + (size_t)n * (4 * C) + c * 4);
    float4 h = *reinterpret_cast<const float4*>(H + (size_t)n * (4 * C) + c * 4);
    float4 b = *reinterpret_cast<const float4*>(bias + c * 4);
    a.x = fmaf(h.x, w, a.x) + b.x;
    a.y = fmaf(h.y, w, a.y) + b.y;
    a.z = fmaf(h.z, w, a.z) + b.z;
    a.w = fmaf(h.w, w, a.w) + b.w;
    if (RELU) {
        a.x = fmaxf(a.x, 0.f); a.y = fmaxf(a.y, 0.f);
        a.z = fmaxf(a.z, 0.f); a.w = fmaxf(a.w, 0.f);
    }
    *reinterpret_cast<float4*>(AGG + (size_t)n * (4 * C) + c * 4) = a;
}

// ---------------------------------------------------------------------------
// Pooling
// ---------------------------------------------------------------------------
__global__ void pool_count(int N) {
    int n = blockIdx.x * 256 + threadIdx.x;
    if (n < N) atomicAdd(&g_counts[g_batch[n]], 1.0f);
}

__global__ void pool_sum(const float* __restrict__ H, float* __restrict__ out, int N) {
    unsigned idx = blockIdx.x * 256u + threadIdx.x;
    unsigned n = idx >> 2;
    unsigned c = idx & 3;
    if (n >= (unsigned)N) return;
    int g = g_batch[n];
    float4 v = *reinterpret_cast<const float4*>(H + (size_t)n * 16 + c * 4);
    float* p = out + (size_t)g * 16 + c * 4;
    asm volatile("red.global.add.v4.f32 [%0], {%1,%2,%3,%4};"
                 :: "l"(p), "f"(v.x), "f"(v.y), "f"(v.z), "f"(v.w)
                 : "memory");
}

__global__ void pool_div(float* __restrict__ out, int G) {
    int i = blockIdx.x * 256 + threadIdx.x;
    if (i < G * 16) {
        float cnt = fmaxf(g_counts[i >> 4], 1.0f);
        out[i] = out[i] / cnt;
    }
}

// ---------------------------------------------------------------------------
// Launch
// ---------------------------------------------------------------------------
static inline int cdiv(int a, int b) { return (a + b - 1) / b; }

extern "C" void kernel_launch(void* const* d_in, const int* in_sizes, int n_in,
                              void* d_out, int out_size) {
    const float* x     = (const float*)d_in[0];
    const void*  ei    = d_in[1];
    const void*  batch = d_in[2];
    const float* W1    = (const float*)d_in[3];
    const float* b1    = (const float*)d_in[4];
    const float* W2    = (const float*)d_in[5];
    const float* b2    = (const float*)d_in[6];
    const float* W3    = (const float*)d_in[7];
    const float* b3    = (const float*)d_in[8];

    int N = in_sizes[0] / 128;
    int E = in_sizes[1] / 2;
    int G = out_size / 16;
    float* out = (float*)d_out;

    float *bufA, *bufB, *counts;
    int *ei_flag, *batch_flag;
    cudaGetSymbolAddress((void**)&bufA, g_bufA);
    cudaGetSymbolAddress((void**)&bufB, g_bufB);
    cudaGetSymbolAddress((void**)&counts, g_counts);
    cudaGetSymbolAddress((void**)&ei_flag, g_ei_is64);
    cudaGetSymbolAddress((void**)&batch_flag, g_batch_is64);

    // --- dtype probes (int32 vs int64 for index tensors) ---
    detect_i64<<<1, 256>>>((const int*)ei, (long long)E, ei_flag);        // first half = E of 2E elems
    detect_i64<<<1, 256>>>((const int*)batch, (long long)N / 2, batch_flag);

    // --- graph prep ---
    prep_edges<<<cdiv(E, 256), 256>>>(ei, E);
    prep_batch<<<cdiv(N, 256), 256>>>(batch, N);
    init_deg<<<cdiv(N, 256), 256>>>(N);
    accum_deg<<<cdiv(E, 256), 256>>>(E);
    compute_dis<<<cdiv(N, 256), 256>>>(N);
    compute_w<<<cdiv(E, 256), 256>>>(E);

    // --- Layer 1: x[N,128] -> bufB[N,64] (relu) ---
    gemm_kernel<128, 64><<<cdiv(N, 128), 128>>>(x, W1, bufA, N);
    zero4_kernel<<<cdiv(N * 16, 256), 256>>>(bufB, N * 16);
    scatter_kernel<16><<<cdiv(E * 16, 256), 256>>>(bufA, bufB, E);
    finalize_kernel<16, true><<<cdiv(N * 16, 256), 256>>>(bufB, bufA, b1, N);

    // --- Layer 2: bufB[N,64] -> bufB[N,64] (relu) ---
    gemm_kernel<64, 64><<<cdiv(N, 128), 128>>>(bufB, W2, bufA, N);
    zero4_kernel<<<cdiv(N * 16, 256), 256>>>(bufB, N * 16);
    scatter_kernel<16><<<cdiv(E * 16, 256), 256>>>(bufA, bufB, E);
    finalize_kernel<16, true><<<cdiv(N * 16, 256), 256>>>(bufB, bufA, b2, N);

    // --- Layer 3: bufB[N,64] -> bufB[N,16] (no relu) ---
    gemm_kernel<64, 16><<<cdiv(N, 128), 128>>>(bufB, W3, bufA, N);
    zero4_kernel<<<cdiv(N * 4, 256), 256>>>(bufB, N * 4);
    scatter_kernel<4><<<cdiv(E * 4, 256), 256>>>(bufA, bufB, E);
    finalize_kernel<4, false><<<cdiv(N * 4, 256), 256>>>(bufB, bufA, b3, N);

    // --- global mean pool ---
    zero4_kernel<<<cdiv(G * 4, 256), 256>>>(out, G * 4);
    zero1_kernel<<<cdiv(G, 256), 256>>>(counts, G);
    pool_count<<<cdiv(N, 256), 256>>>(N);
    pool_sum<<<cdiv(N * 4, 256), 256>>>(bufB, out, N);
    pool_div<<<cdiv(G * 16, 256), 256>>>(out, G);
}